// round 6
// baseline (speedup 1.0000x reference)
#include <cuda_runtime.h>
#include <cstdint>

// VectorQuantizer: tf32 mma.sync filter + exact fp32 recheck.
// R6: fused A-fragment build (no zprep), smem cand list, persistent z stage,
// TPB=256 / 128 CTAs = one wave. Math bitwise-identical to the R5 passer.

#define NUM_CODES 1024
#define DIM       64
#define HW        1024
#define N_VEC     32768
#define N_TOTAL   2097152
#define TPB       256
#define NBLOCKS   128
#define NCHUNK    16          // 16 chunks x 64 codes
#define EPS2      1.5e-3f     // 2.1x worst-case tf32 score-error bound
#define MAXCAND   32
#define DPAD      68          // row stride (f32): 16B-aligned, conflict-free

// dynamic smem layout (bytes)
#define OFF_B     0           // 2 x 4096 u32            = 32768
#define OFF_Z     32768       // 256 rows x 68 f32       = 69632
#define OFF_D     102400      // 8 w x 32 x 68 f32       = 69632
#define OFF_CN    172032      // 1024 f32                = 4096
#define OFF_CAND  176128      // 32 x 256 i32            = 32768
#define OFF_RED   208896      // 256 f32                 = 1024
#define SMEM_TOTAL 209920

__device__ float    g_cnorm[NUM_CODES];
__device__ float    g_partial[NBLOCKS];
__device__ uint32_t g_bfrag[NUM_CODES * DIM];   // 256 KB fragment-ordered tf32

__device__ __forceinline__ uint32_t f2tf32(float f) {
    uint32_t u; asm("cvt.rna.tf32.f32 %0, %1;" : "=r"(u) : "f"(f)); return u;
}
// m16n8k8 row.col tf32: A 4 regs, B 2 regs, D 4 f32 (accumulate in place)
__device__ __forceinline__ void mma_tf32(float* d, const uint32_t* a,
                                         uint32_t b0, uint32_t b1) {
    asm("mma.sync.aligned.m16n8k8.row.col.f32.tf32.tf32.f32 "
        "{%0,%1,%2,%3}, {%4,%5,%6,%7}, {%8,%9}, {%0,%1,%2,%3};"
        : "+f"(d[0]), "+f"(d[1]), "+f"(d[2]), "+f"(d[3])
        : "r"(a[0]), "r"(a[1]), "r"(a[2]), "r"(a[3]), "r"(b0), "r"(b1));
}

// exact fp32 score, byte-identical sequence to the round-2 passing kernel;
// z values come from the smem stage (same bits as the gmem loads).
__device__ __forceinline__ float exact_score(const float* __restrict__ cb, int k,
                                             const float* __restrict__ zrow,
                                             float zn, float cn) {
    const float4* row = (const float4*)(cb + (size_t)k * DIM);
    float d = 0.0f;
#pragma unroll
    for (int i = 0; i < 16; i++) {
        float4 a = row[i];
        d = fmaf(a.x, zrow[4 * i + 0], d);
        d = fmaf(a.y, zrow[4 * i + 1], d);
        d = fmaf(a.z, zrow[4 * i + 2], d);
        d = fmaf(a.w, zrow[4 * i + 3], d);
    }
    return __fadd_rn(__fsub_rn(zn, __fmul_rn(2.0f, d)), cn);
}

// ---------------------------------------------------------------------------
// Prep 0: codebook row norms (one warp per code).
// ---------------------------------------------------------------------------
__global__ void cnorm_kernel(const float* __restrict__ cb) {
    int w = (blockIdx.x * blockDim.x + threadIdx.x) >> 5;
    int l = threadIdx.x & 31;
    if (w < NUM_CODES) {
        float2 v = *(const float2*)(cb + (size_t)w * DIM + 2 * l);
        float s = fmaf(v.x, v.x, v.y * v.y);
#pragma unroll
        for (int off = 16; off > 0; off >>= 1)
            s += __shfl_down_sync(0xFFFFFFFFu, s, off);
        if (l == 0) g_cnorm[w] = s;
    }
}

// ---------------------------------------------------------------------------
// Prep 1: codebook -> tf32 B fragments (unchanged layout from R5).
// o = ((t*8 + j)*8 + kk)*64 + lane*2 + h ; code=t*64+j*8+(lane>>2),
// dim = kk*8 + (lane&3) + h*4
// ---------------------------------------------------------------------------
__global__ void bprep_kernel(const float* __restrict__ cb) {
    int o = blockIdx.x * blockDim.x + threadIdx.x;
    if (o < NUM_CODES * DIM) {
        int h = o & 1, lane = (o >> 1) & 31, kk = (o >> 6) & 7;
        int j = (o >> 9) & 7, t = o >> 12;
        int code = t * 64 + j * 8 + (lane >> 2);
        int dim  = kk * 8 + (lane & 3) + h * 4;
        g_bfrag[o] = f2tf32(cb[(size_t)code * DIM + dim]);
    }
}

// ---------------------------------------------------------------------------
// Main: stage z -> build A frags -> mma filter -> exact recheck -> out + loss
// ---------------------------------------------------------------------------
__global__ void __launch_bounds__(TPB, 1)
vq_main_kernel(const float* __restrict__ z,
               const float* __restrict__ cb,
               float* __restrict__ out) {
    extern __shared__ __align__(16) unsigned char smem[];
    uint32_t* s_b   = (uint32_t*)(smem + OFF_B);
    float*    s_z   = (float*)(smem + OFF_Z);
    float*    s_d   = (float*)(smem + OFF_D);
    float*    s_cn  = (float*)(smem + OFF_CN);
    int*      s_cand= (int*)(smem + OFF_CAND);
    float*    s_red = (float*)(smem + OFF_RED);

    const int tid  = threadIdx.x;
    const int w    = tid >> 5;
    const int lane = tid & 31;
    const int gid  = lane >> 2, tig = lane & 3;
    const int n    = blockIdx.x * TPB + tid;
    const int b    = n >> 10;
    const int hw   = n & (HW - 1);

    // Load z vector once (coalesced strided), compute zn in the round-2
    // sequential order, and stage the row into smem (stride 68).
    const float* zp = z + (size_t)b * DIM * HW + hw;
    float* zrow = s_z + tid * DPAD;
    float zn = 0.0f;
#pragma unroll
    for (int c = 0; c < DIM; c++) {
        float v = zp[(size_t)c * HW];
        zn = fmaf(v, v, zn);
        zrow[c] = v;
    }

    // code norms -> smem
#pragma unroll
    for (int i = 0; i < NUM_CODES / TPB; i++)
        s_cn[tid + i * TPB] = g_cnorm[tid + i * TPB];
    __syncthreads();

    // Build tf32 A fragments from the z stage (same cvt.rna as R5's zprep):
    // a[r]: r0=(gid,tig) r1=(gid+8,tig) r2=(gid,tig+4) r3=(gid+8,tig+4)
    uint32_t afr[2][8][4];
#pragma unroll
    for (int m = 0; m < 2; m++)
#pragma unroll
        for (int kk = 0; kk < 8; kk++)
#pragma unroll
            for (int r = 0; r < 4; r++) {
                int row = w * 32 + m * 16 + gid + ((r & 1) << 3);
                int col = kk * 8 + tig + ((r >> 1) << 2);
                afr[m][kk][r] = f2tf32(s_z[row * DPAD + col]);
            }

    // stage B chunk 0 into buf 0 (1024 uint4, 4 per thread)
    const uint4* bsrc = (const uint4*)g_bfrag;
    {
        uint4* bdst = (uint4*)s_b;
#pragma unroll
        for (int i = 0; i < 4; i++) bdst[i * TPB + tid] = bsrc[i * TPB + tid];
    }
    __syncthreads();

    float runmin = 3.402823466e38f, thr = 3.402823466e38f;
    int cnt = 0;
    float* dw = s_d + w * 32 * DPAD;

#pragma unroll 1
    for (int t = 0; t < NCHUNK; t++) {
        // prefetch next chunk into regs (overlaps mma)
        uint4 pf[4];
        if (t + 1 < NCHUNK) {
#pragma unroll
            for (int i = 0; i < 4; i++)
                pf[i] = bsrc[(t + 1) * 1024 + i * TPB + tid];
        }

        const uint32_t* bbuf = s_b + (t & 1) * 4096;
#pragma unroll
        for (int j = 0; j < 8; j++) {
            float d0[4] = {0.f, 0.f, 0.f, 0.f}, d1[4] = {0.f, 0.f, 0.f, 0.f};
#pragma unroll
            for (int kk = 0; kk < 8; kk++) {
                uint2 bb = *(const uint2*)&bbuf[((j * 8 + kk) * 32 + lane) * 2];
                mma_tf32(d0, afr[0][kk], bb.x, bb.y);
                mma_tf32(d1, afr[1][kk], bb.x, bb.y);
            }
            *(float2*)&dw[(gid +  0) * DPAD + j * 8 + tig * 2] = make_float2(d0[0], d0[1]);
            *(float2*)&dw[(gid +  8) * DPAD + j * 8 + tig * 2] = make_float2(d0[2], d0[3]);
            *(float2*)&dw[(gid + 16) * DPAD + j * 8 + tig * 2] = make_float2(d1[0], d1[1]);
            *(float2*)&dw[(gid + 24) * DPAD + j * 8 + tig * 2] = make_float2(d1[2], d1[3]);
        }
        __syncwarp();

        // serial ascending-k filter on this thread's own row (candidates->smem)
        const float* drow = dw + lane * DPAD;
        const float* cnp  = s_cn + t * 64;
#pragma unroll
        for (int c4 = 0; c4 < 16; c4++) {
            float4 dd = *(const float4*)&drow[c4 * 4];
            float4 cc = *(const float4*)&cnp[c4 * 4];
            float s0 = fmaf(-2.0f, dd.x, cc.x);
            float s1 = fmaf(-2.0f, dd.y, cc.y);
            float s2 = fmaf(-2.0f, dd.z, cc.z);
            float s3 = fmaf(-2.0f, dd.w, cc.w);
            int kb = t * 64 + c4 * 4;
            if (s0 < thr) { if (cnt < MAXCAND) s_cand[cnt * TPB + tid] = kb + 0; cnt++;
                            if (s0 < runmin) { runmin = s0; thr = runmin + EPS2; } }
            if (s1 < thr) { if (cnt < MAXCAND) s_cand[cnt * TPB + tid] = kb + 1; cnt++;
                            if (s1 < runmin) { runmin = s1; thr = runmin + EPS2; } }
            if (s2 < thr) { if (cnt < MAXCAND) s_cand[cnt * TPB + tid] = kb + 2; cnt++;
                            if (s2 < runmin) { runmin = s2; thr = runmin + EPS2; } }
            if (s3 < thr) { if (cnt < MAXCAND) s_cand[cnt * TPB + tid] = kb + 3; cnt++;
                            if (s3 < runmin) { runmin = s3; thr = runmin + EPS2; } }
        }

        // commit prefetched chunk to the other buffer
        if (t + 1 < NCHUNK) {
            uint4* bdst = (uint4*)(s_b + ((t + 1) & 1) * 4096);
#pragma unroll
            for (int i = 0; i < 4; i++) bdst[i * TPB + tid] = pf[i];
        }
        __syncthreads();
    }

    // exact selection among candidates (ascending k, strict < = first index)
    float best = 3.402823466e38f;
    int bestk = 0;
    if (cnt <= MAXCAND) {
        for (int jj = 0; jj < cnt; jj++) {
            int k = s_cand[jj * TPB + tid];
            float s = exact_score(cb, k, zrow, zn, s_cn[k]);
            if (s < best) { best = s; bestk = k; }
        }
    } else {  // deterministic fallback (P ~ 0): full exact scan
        for (int k = 0; k < NUM_CODES; k++) {
            float s = exact_score(cb, k, zrow, zn, s_cn[k]);
            if (s < best) { best = s; bestk = k; }
        }
    }

    // gather + straight-through output + loss (round-2 identical rounding)
    const float* crow = cb + (size_t)bestk * DIM;
    float* op = out + (size_t)b * DIM * HW + hw;
    float lsum = 0.0f;
#pragma unroll
    for (int c = 0; c < DIM; c++) {
        float q = crow[c];
        float zv = zrow[c];
        float d = __fsub_rn(q, zv);
        lsum = fmaf(d, d, lsum);
        op[(size_t)c * HW] = __fadd_rn(zv, d);
    }

    __syncthreads();
    s_red[tid] = lsum;
    __syncthreads();
#pragma unroll
    for (int s = TPB / 2; s > 0; s >>= 1) {
        if (tid < s) s_red[tid] += s_red[tid + s];
        __syncthreads();
    }
    if (tid == 0) g_partial[blockIdx.x] = s_red[0];
}

// ---------------------------------------------------------------------------
__global__ void loss_kernel(float* __restrict__ loss_out) {
    __shared__ float s_red[NBLOCKS];
    int tid = threadIdx.x;
    s_red[tid] = g_partial[tid];
    __syncthreads();
#pragma unroll
    for (int s = NBLOCKS / 2; s > 0; s >>= 1) {
        if (tid < s) s_red[tid] += s_red[tid + s];
        __syncthreads();
    }
    if (tid == 0) loss_out[0] = s_red[0] * (1.25f / (float)N_TOTAL);
}

// ---------------------------------------------------------------------------
extern "C" void kernel_launch(void* const* d_in, const int* in_sizes, int n_in,
                              void* d_out, int out_size) {
    const float* z  = (const float*)d_in[0];
    const float* cb = (const float*)d_in[1];
    float* out = (float*)d_out;

    cudaFuncSetAttribute(vq_main_kernel,
                         cudaFuncAttributeMaxDynamicSharedMemorySize, SMEM_TOTAL);

    cnorm_kernel<<<NUM_CODES * 32 / 256, 256>>>(cb);
    bprep_kernel<<<NUM_CODES * DIM / 256, 256>>>(cb);
    vq_main_kernel<<<NBLOCKS, TPB, SMEM_TOTAL>>>(z, cb, out);
    if (out_size > N_TOTAL) {
        loss_kernel<<<1, NBLOCKS>>>(out + (out_size - 1));
    }
}